// round 5
// baseline (speedup 1.0000x reference)
#include <cuda_runtime.h>
#include <cstdint>
#include <cstddef>

// Shapes: B=1, H=12, S=384, V=64, D=768
// Outputs (fp32, concatenated): importance[384,384] @0, tv_norm[384,384] @147456,
// tv_std[384,384,768] @294912, resultant[384,768] @113541120

#define OFF_NORM 147456
#define OFF_TV   294912
#define OFF_RES  113541120u

// ---------------- device scratch (no allocations allowed) -------------------
__device__ float g_Tc[12*384*768];    // [h][s][d] centered*gamma per-head projection
__device__ float g_At[384*4608];      // [k][h*384+s] = attn[h,k,s]  (GEMM A)
__device__ float g_hc[384*768];       // (hidden - mean_d)*w_ln
__device__ float g_resmn[384*768];    // eps - resultant
__device__ float g_part[16*384*768];  // split-K GEMM partials
__device__ float g_biasc[768];        // (bias - mean)*w_ln
__device__ float g_inv[384];          // 1/std(pre_ln, ddof=1)

// ---------------- f32x2 helpers ---------------------------------------------
__device__ __forceinline__ unsigned long long pack2(float lo, float hi){
    unsigned long long r; asm("mov.b64 %0, {%1, %2};" : "=l"(r) : "f"(lo), "f"(hi)); return r;
}
__device__ __forceinline__ unsigned long long dup2(float a){
    unsigned long long r; asm("mov.b64 %0, {%1, %1};" : "=l"(r) : "f"(a)); return r;
}
__device__ __forceinline__ void unpack2(unsigned long long v, float& lo, float& hi){
    asm("mov.b64 {%0, %1}, %2;" : "=f"(lo), "=f"(hi) : "l"(v));
}
__device__ __forceinline__ void fma2(unsigned long long& acc, unsigned long long a, unsigned long long b){
    asm("fma.rn.f32x2 %0, %1, %2, %0;" : "+l"(acc) : "l"(a), "l"(b));
}
__device__ __forceinline__ unsigned long long add2(unsigned long long a, unsigned long long b){
    unsigned long long r; asm("add.rn.f32x2 %0, %1, %2;" : "=l"(r) : "l"(a), "l"(b)); return r;
}
__device__ __forceinline__ unsigned long long mul2(unsigned long long a, unsigned long long b){
    unsigned long long r; asm("mul.rn.f32x2 %0, %1, %2;" : "=l"(r) : "l"(a), "l"(b)); return r;
}

// ---------------- K1: row stats ----------------------------------------------
__global__ void k_stats(const float* __restrict__ preln, const float* __restrict__ hidden,
                        const float* __restrict__ dbias, const float* __restrict__ wln){
    __shared__ float w1[8], w2[8], sres[2];
    int b = blockIdx.x, t = threadIdx.x, lane = t & 31, wid = t >> 5;
    if (b < 384){
        const float* row = preln + (size_t)b*768;
        float s1=0.f, s2=0.f;
        for (int d=t; d<768; d+=256){ float x=row[d]; s1+=x; s2=fmaf(x,x,s2); }
        for (int o=16;o;o>>=1){ s1+=__shfl_xor_sync(~0u,s1,o); s2+=__shfl_xor_sync(~0u,s2,o); }
        if (lane==0){ w1[wid]=s1; w2[wid]=s2; }
        __syncthreads();
        if (t==0){
            float a=0.f,c=0.f;
            #pragma unroll
            for (int j=0;j<8;j++){ a+=w1[j]; c+=w2[j]; }
            float mean = a*(1.0f/768.0f);
            float var  = (c - a*mean)*(1.0f/767.0f);
            float inv  = rsqrtf(var);
            g_inv[b]=inv; sres[0]=inv;
        }
        __syncthreads();
        const float* hr = hidden + (size_t)b*768;
        float hs=0.f;
        for (int d=t; d<768; d+=256) hs += hr[d];
        for (int o=16;o;o>>=1) hs += __shfl_xor_sync(~0u,hs,o);
        __syncthreads();
        if (lane==0) w1[wid]=hs;
        __syncthreads();
        if (t==0){
            float a=0.f;
            #pragma unroll
            for (int j=0;j<8;j++) a+=w1[j];
            sres[1]=a*(1.0f/768.0f);
        }
        __syncthreads();
        float hmean = sres[1];
        for (int d=t; d<768; d+=256)
            g_hc[(size_t)b*768+d] = (hr[d]-hmean)*wln[d];
    } else {
        float s=0.f;
        for (int d=t; d<768; d+=256) s += dbias[d];
        for (int o=16;o;o>>=1) s += __shfl_xor_sync(~0u,s,o);
        if (lane==0) w1[wid]=s;
        __syncthreads();
        if (t==0){
            float a=0.f;
            #pragma unroll
            for (int j=0;j<8;j++) a+=w1[j];
            sres[0]=a*(1.0f/768.0f);
        }
        __syncthreads();
        float mean = sres[0];
        for (int d=t; d<768; d+=256) g_biasc[d] = (dbias[d]-mean)*wln[d];
    }
}

// ---------------- K2: Tc[h][s][d] = (value_h @ W_h^T  centered) * w_ln -------
__global__ __launch_bounds__(256) void k_tc(const float* __restrict__ value,
                                            const float* __restrict__ dw,
                                            const float* __restrict__ wln){
    __shared__ float val[12*64];
    __shared__ float T[12*768];
    __shared__ float means[12];
    int s0 = blockIdx.x*12, h = blockIdx.y, t = threadIdx.x;
    if (t < 192)
        ((float4*)val)[t] = ((const float4*)(value + ((size_t)h*384 + s0)*64))[t];
    __syncthreads();
    const unsigned long long* val2 = (const unsigned long long*)val;
    #pragma unroll 1
    for (int g=0; g<3; g++){
        int d = g*256 + t;
        unsigned long long w2r[32];
        const unsigned long long* wr = (const unsigned long long*)(dw + ((size_t)d*12 + h)*64);
        #pragma unroll
        for (int i=0;i<32;i++) w2r[i]=wr[i];
        #pragma unroll 1
        for (int s=0;s<12;s++){
            unsigned long long acc = 0ull;
            #pragma unroll
            for (int i=0;i<32;i++) fma2(acc, w2r[i], val2[s*32+i]);
            float lo,hi; unpack2(acc,lo,hi);
            T[s*768 + d] = lo + hi;
        }
    }
    __syncthreads();
    int w = t>>5, l = t&31;
    for (int s=w; s<12; s+=8){
        float sum=0.f;
        for (int i=l; i<768; i+=32) sum += T[s*768+i];
        #pragma unroll
        for (int o=16;o;o>>=1) sum += __shfl_xor_sync(~0u,sum,o);
        if (l==0) means[s] = sum*(1.0f/768.0f);
    }
    __syncthreads();
    #pragma unroll 1
    for (int g=0; g<3; g++){
        int d = g*256+t; float wl = wln[d];
        #pragma unroll
        for (int s=0;s<12;s++)
            g_Tc[((size_t)h*384 + s0 + s)*768 + d] = (T[s*768+d]-means[s])*wl;
    }
}

// ---------------- K3: At[k][h*384+s] = attn[h][k][s]  (row copies) -----------
__global__ void k_at(const float* __restrict__ attn){
    int k = blockIdx.x, t = threadIdx.x;
    float4* dst = (float4*)(g_At + (size_t)k*4608);
    for (int idx=t; idx<1152; idx+=256){
        int h = idx/96, j = idx - h*96;
        dst[h*96 + j] = ((const float4*)(attn + ((size_t)h*384 + k)*384))[j];
    }
}

// ---------------- K4: split-K SGEMM  C[384,768] = At[384,4608] @ Tc ----------
// 64x128 tile, BK=16, split-K=16, 256 threads, thread = 4m x 8n.
__global__ __launch_bounds__(256) void k_gemm(){
    __shared__ float As[16*68];    // [kk][m] transposed, padded
    __shared__ float Bs[16*128];   // [kk][n]
    int m0 = blockIdx.x*64, n0 = blockIdx.y*128, z = blockIdx.z;
    int K0 = z*288;
    int t = threadIdx.x;
    int tym = t>>4, tx = t&15;
    unsigned long long acc[4][4];
    #pragma unroll
    for (int i=0;i<4;i++)
        #pragma unroll
        for (int j=0;j<4;j++) acc[i][j]=0ull;
    for (int ks=0; ks<18; ks++){
        int kb = K0 + ks*16;
        {
            int r = t>>2, c = (t&3)*4;
            float4 a4 = *(const float4*)(g_At + (size_t)(m0+r)*4608 + kb + c);
            As[(c+0)*68+r]=a4.x; As[(c+1)*68+r]=a4.y;
            As[(c+2)*68+r]=a4.z; As[(c+3)*68+r]=a4.w;
        }
        #pragma unroll
        for (int rep=0; rep<2; rep++){
            int idx = t + rep*256;
            int rb = idx>>5, cb = (idx&31)*4;
            *(float4*)&Bs[rb*128+cb] = *(const float4*)(g_Tc + (size_t)(kb+rb)*768 + n0 + cb);
        }
        __syncthreads();
        #pragma unroll
        for (int kk=0; kk<16; kk++){
            float4 a  = *(float4*)&As[kk*68 + tym*4];
            float4 b1 = *(float4*)&Bs[kk*128 + tx*8];
            float4 b2 = *(float4*)&Bs[kk*128 + tx*8 + 4];
            unsigned long long bv0=pack2(b1.x,b1.y), bv1=pack2(b1.z,b1.w);
            unsigned long long bv2=pack2(b2.x,b2.y), bv3=pack2(b2.z,b2.w);
            float av[4]={a.x,a.y,a.z,a.w};
            #pragma unroll
            for (int i=0;i<4;i++){
                unsigned long long ad = dup2(av[i]);
                fma2(acc[i][0],ad,bv0); fma2(acc[i][1],ad,bv1);
                fma2(acc[i][2],ad,bv2); fma2(acc[i][3],ad,bv3);
            }
        }
        __syncthreads();
    }
    #pragma unroll
    for (int i=0;i<4;i++){
        int row = m0 + tym*4 + i;
        float* dst = g_part + ((size_t)z*384 + row)*768 + n0 + tx*8;
        ulonglong2 v0; v0.x=acc[i][0]; v0.y=acc[i][1];
        ulonglong2 v1; v1.x=acc[i][2]; v1.y=acc[i][3];
        *(ulonglong2*)dst = v0;
        *(ulonglong2*)(dst+4) = v1;
    }
}

// ---------------- K5: resultant + resmn --------------------------------------
__global__ void k_res(const float* __restrict__ lnb, float* __restrict__ out_res){
    int k = blockIdx.x;
    float inv = g_inv[k];
    for (int d=threadIdx.x; d<768; d+=256){
        float s = 0.f;
        #pragma unroll
        for (int z=0; z<16; z++) s += g_part[((size_t)z*384 + k)*768 + d];
        float ao = s + g_hc[(size_t)k*768 + d] + g_biasc[d];
        float r  = ao*inv + lnb[d];
        out_res[(size_t)k*768 + d] = r;
        g_resmn[(size_t)k*768 + d] = 1e-6f - r;
    }
}

// ---------------- K6: main fused kernel --------------------------------------
// block = (s, k-half). 384 thr = 2 groups x 192 (each thread owns 4 d).
// Per-kk scalar partials go to smem; every 8 kk, warps cooperatively reduce
// rows of 192 and write importance / tv_norm directly. No per-kk butterflies.
__global__ __launch_bounds__(384) void k_main(const float* __restrict__ attn,
                                              float* __restrict__ out){
    __shared__ unsigned long long cs2[192*12];  // dup'd attn[h,k,s]*inv[k], [kk][h]
    __shared__ float rn[2][8][192];             // norm^2 partials [grp][j][thread]
    __shared__ float ra[2][8][192];             // abs-sum partials
    int s = blockIdx.x;
    int kbase = blockIdx.y*192;
    int t = threadIdx.x;

    // stage duplicated coefficients
    for (int idx=t; idx<2304; idx+=384){
        int kk = idx/12, h = idx - kk*12;
        int k = kbase + kk;
        float c = attn[(size_t)h*147456 + (size_t)k*384 + s] * g_inv[k];
        cs2[idx] = dup2(c);
    }

    int grp = t/192;
    int tt  = t - grp*192;
    int d0  = tt*4;

    // register-resident Tc[h][d0..d0+3]
    unsigned long long tca[12], tcb[12];
    #pragma unroll
    for (int h=0; h<12; h++){
        ulonglong2 v = *(const ulonglong2*)(g_Tc + ((size_t)h*384 + s)*768 + d0);
        tca[h]=v.x; tcb[h]=v.y;
    }
    unsigned long long hca, hcb;
    {
        ulonglong2 v = *(const ulonglong2*)(g_hc + (size_t)s*768 + d0);
        unsigned long long iv = dup2(g_inv[s]);
        hca = mul2(v.x, iv); hcb = mul2(v.y, iv);
    }
    __syncthreads();

    int wid = t>>5, lane = t&31;
    float* out_tv = out + OFF_TV;
    const unsigned long long MSK = 0x7FFFFFFF7FFFFFFFULL;

    int kk0 = grp*96;
    ulonglong2 rv = *(const ulonglong2*)(g_resmn + (size_t)(kbase+kk0)*768 + d0);
    #pragma unroll 1
    for (int batch=0; batch<12; batch++){
        #pragma unroll 2
        for (int j=0; j<8; j++){
            int kkl = batch*8 + j;                  // 0..95 within group
            int k   = kbase + kk0 + kkl;
            int kkn = (kkl+1 < 96) ? kkl+1 : kkl;
            ulonglong2 rvn = *(const ulonglong2*)(g_resmn + (size_t)(kbase+kk0+kkn)*768 + d0);

            // 12 pre-duplicated coefficients: 6 x LDS.128
            const ulonglong2* cp = (const ulonglong2*)&cs2[(kk0+kkl)*12];
            ulonglong2 c01 = cp[0], c23 = cp[1], c45 = cp[2];
            ulonglong2 c67 = cp[3], c89 = cp[4], cAB = cp[5];
            unsigned long long cd[12] = { c01.x,c01.y, c23.x,c23.y, c45.x,c45.y,
                                          c67.x,c67.y, c89.x,c89.y, cAB.x,cAB.y };

            unsigned long long acc0, acc1;
            if (k==s){ acc0 = hca; acc1 = hcb; } else { acc0 = 0ull; acc1 = 0ull; }
            #pragma unroll
            for (int h=0; h<12; h++){
                fma2(acc0, cd[h], tca[h]);
                fma2(acc1, cd[h], tcb[h]);
            }

            // store tv_std (16B per thread, contiguous per warp)
            ulonglong2 st; st.x=acc0; st.y=acc1;
            *(ulonglong2*)(out_tv + ((size_t)k*384 + s)*768 + d0) = st;

            // norm^2 partial
            unsigned long long n2 = 0ull;
            fma2(n2, acc0, acc0);
            fma2(n2, acc1, acc1);
            // |tv_std - resultant + eps| partial
            unsigned long long df0 = add2(acc0, rv.x) & MSK;
            unsigned long long df1 = add2(acc1, rv.y) & MSK;
            unsigned long long aa  = add2(df0, df1);

            float nlo,nhi,alo,ahi;
            unpack2(n2,nlo,nhi); unpack2(aa,alo,ahi);
            rn[grp][j][tt] = nlo+nhi;
            ra[grp][j][tt] = alo+ahi;
            rv = rvn;
        }
        __syncthreads();
        // 32 reduction tasks: {norm,abs} x {grp0,grp1} x 8 rows, 192 floats each
        #pragma unroll 1
        for (int task=wid; task<32; task+=12){
            int arr = task>>4, rem = task&15, g2 = rem>>3, j = rem&7;
            const float* buf = arr ? &ra[g2][j][0] : &rn[g2][j][0];
            float v = buf[lane] + buf[lane+32] + buf[lane+64]
                    + buf[lane+96] + buf[lane+128] + buf[lane+160];
            #pragma unroll
            for (int o=16;o;o>>=1) v += __shfl_xor_sync(~0u,v,o);
            if (lane==0){
                int k = kbase + g2*96 + batch*8 + j;
                if (arr) out[(size_t)k*384 + s] = -v;                    // importance
                else     out[OFF_NORM + (size_t)k*384 + s] = sqrtf(v);   // tv_norm
            }
        }
        __syncthreads();
    }
}

// ---------------- launch ------------------------------------------------------
extern "C" void kernel_launch(void* const* d_in, const int* in_sizes, int n_in,
                              void* d_out, int out_size){
    (void)in_sizes; (void)n_in; (void)out_size;
    const float* value  = (const float*)d_in[0];
    const float* attn   = (const float*)d_in[1];
    const float* hidden = (const float*)d_in[2];
    const float* preln  = (const float*)d_in[3];
    const float* dw     = (const float*)d_in[4];
    const float* dbias  = (const float*)d_in[5];
    const float* wln    = (const float*)d_in[6];
    const float* lnb    = (const float*)d_in[7];
    float* out = (float*)d_out;

    k_stats<<<385, 256>>>(preln, hidden, dbias, wln);
    k_tc<<<dim3(32,12), 256>>>(value, dw, wln);
    k_at<<<384, 256>>>(attn);
    k_gemm<<<dim3(6,6,16), 256>>>();
    k_res<<<384, 256>>>(lnb, out + OFF_RES);
    k_main<<<dim3(384,2), 384>>>(attn, out);
}

// round 7
// speedup vs baseline: 1.3511x; 1.3511x over previous
#include <cuda_runtime.h>
#include <cstdint>
#include <cstddef>

// Shapes: B=1, H=12, S=384, V=64, D=768
// Outputs (fp32, concatenated): importance[384,384] @0, tv_norm[384,384] @147456,
// tv_std[384,384,768] @294912, resultant[384,768] @113541120

#define OFF_NORM 147456
#define OFF_TV   294912
#define OFF_RES  113541120u

// ---------------- device scratch (no allocations allowed) -------------------
__device__ __align__(16) float g_Tc[12*384*768];    // [h][s][d]
__device__ __align__(16) float g_At[384*4608];      // [k][h*384+s] = attn[h,k,s]
__device__ __align__(16) float g_hc[384*768];       // (hidden - mean_d)*w_ln
__device__ __align__(16) float g_resmn[384*768];    // eps - resultant
__device__ __align__(16) float g_part[8*384*768];   // split-K GEMM partials
__device__ __align__(16) float g_biasc[768];        // (bias - mean)*w_ln
__device__ __align__(16) float g_inv[384];          // 1/std(pre_ln, ddof=1)

// ---------------- f32x2 helpers ---------------------------------------------
__device__ __forceinline__ unsigned long long pack2(float lo, float hi){
    unsigned long long r; asm("mov.b64 %0, {%1, %2};" : "=l"(r) : "f"(lo), "f"(hi)); return r;
}
__device__ __forceinline__ unsigned long long dup2(float a){
    unsigned long long r; asm("mov.b64 %0, {%1, %1};" : "=l"(r) : "f"(a)); return r;
}
__device__ __forceinline__ void unpack2(unsigned long long v, float& lo, float& hi){
    asm("mov.b64 {%0, %1}, %2;" : "=f"(lo), "=f"(hi) : "l"(v));
}
__device__ __forceinline__ void fma2(unsigned long long& acc, unsigned long long a, unsigned long long b){
    asm("fma.rn.f32x2 %0, %1, %2, %0;" : "+l"(acc) : "l"(a), "l"(b));
}
__device__ __forceinline__ unsigned long long add2(unsigned long long a, unsigned long long b){
    unsigned long long r; asm("add.rn.f32x2 %0, %1, %2;" : "=l"(r) : "l"(a), "l"(b)); return r;
}
__device__ __forceinline__ unsigned long long mul2(unsigned long long a, unsigned long long b){
    unsigned long long r; asm("mul.rn.f32x2 %0, %1, %2;" : "=l"(r) : "l"(a), "l"(b)); return r;
}

// ---------------- K1: fused prep (stats | attn-transpose | Tc) ---------------
// blocks 0..384   : row stats (inv_std, hc, biasc)
// blocks 385..768 : At[k][h*384+s] = attn[h][k][s]
// blocks 769..1152: Tc[h][s][d]
__global__ __launch_bounds__(256) void k_prep(const float* __restrict__ preln,
                                              const float* __restrict__ hidden,
                                              const float* __restrict__ dbias,
                                              const float* __restrict__ wln,
                                              const float* __restrict__ attn,
                                              const float* __restrict__ value,
                                              const float* __restrict__ dw){
    int bid = blockIdx.x, t = threadIdx.x;
    if (bid <= 384){
        // ---- stats part ----
        __shared__ float w1[8], w2[8], sres[2];
        int lane = t & 31, wid = t >> 5;
        int b = bid;
        if (b < 384){
            const float* row = preln + (size_t)b*768;
            float s1=0.f, s2=0.f;
            for (int d=t; d<768; d+=256){ float x=row[d]; s1+=x; s2=fmaf(x,x,s2); }
            for (int o=16;o;o>>=1){ s1+=__shfl_xor_sync(~0u,s1,o); s2+=__shfl_xor_sync(~0u,s2,o); }
            if (lane==0){ w1[wid]=s1; w2[wid]=s2; }
            __syncthreads();
            if (t==0){
                float a=0.f,c=0.f;
                #pragma unroll
                for (int j=0;j<8;j++){ a+=w1[j]; c+=w2[j]; }
                float mean = a*(1.0f/768.0f);
                float var  = (c - a*mean)*(1.0f/767.0f);
                float inv  = rsqrtf(var);
                g_inv[b]=inv; sres[0]=inv;
            }
            __syncthreads();
            const float* hr = hidden + (size_t)b*768;
            float hs=0.f;
            for (int d=t; d<768; d+=256) hs += hr[d];
            for (int o=16;o;o>>=1) hs += __shfl_xor_sync(~0u,hs,o);
            __syncthreads();
            if (lane==0) w1[wid]=hs;
            __syncthreads();
            if (t==0){
                float a=0.f;
                #pragma unroll
                for (int j=0;j<8;j++) a+=w1[j];
                sres[1]=a*(1.0f/768.0f);
            }
            __syncthreads();
            float hmean = sres[1];
            for (int d=t; d<768; d+=256)
                g_hc[(size_t)b*768+d] = (hr[d]-hmean)*wln[d];
        } else {
            float s=0.f;
            for (int d=t; d<768; d+=256) s += dbias[d];
            for (int o=16;o;o>>=1) s += __shfl_xor_sync(~0u,s,o);
            if (lane==0) w1[wid]=s;
            __syncthreads();
            if (t==0){
                float a=0.f;
                #pragma unroll
                for (int j=0;j<8;j++) a+=w1[j];
                sres[0]=a*(1.0f/768.0f);
            }
            __syncthreads();
            float mean = sres[0];
            for (int d=t; d<768; d+=256) g_biasc[d] = (dbias[d]-mean)*wln[d];
        }
    } else if (bid <= 768){
        // ---- attn transpose part ----
        int k = bid - 385;
        float4* dst = (float4*)(g_At + (size_t)k*4608);
        for (int idx=t; idx<1152; idx+=256){
            int h = idx/96, j = idx - h*96;
            dst[h*96 + j] = ((const float4*)(attn + ((size_t)h*384 + k)*384))[j];
        }
    } else {
        // ---- Tc part ----
        __shared__ __align__(16) float val[12*64];
        __shared__ __align__(16) float T[12*768];
        __shared__ float means[12];
        int i = bid - 769;           // 0..383
        int s0 = (i & 31)*12, h = i >> 5;
        if (t < 192)
            ((float4*)val)[t] = ((const float4*)(value + ((size_t)h*384 + s0)*64))[t];
        __syncthreads();
        const unsigned long long* val2 = (const unsigned long long*)val;
        #pragma unroll 1
        for (int g=0; g<3; g++){
            int d = g*256 + t;
            unsigned long long w2r[32];
            const unsigned long long* wr = (const unsigned long long*)(dw + ((size_t)d*12 + h)*64);
            #pragma unroll
            for (int q=0;q<32;q++) w2r[q]=wr[q];
            #pragma unroll 1
            for (int s=0;s<12;s++){
                unsigned long long acc = 0ull;
                #pragma unroll
                for (int q=0;q<32;q++) fma2(acc, w2r[q], val2[s*32+q]);
                float lo,hi; unpack2(acc,lo,hi);
                T[s*768 + d] = lo + hi;
            }
        }
        __syncthreads();
        int w = t>>5, l = t&31;
        for (int s=w; s<12; s+=8){
            float sum=0.f;
            for (int q=l; q<768; q+=32) sum += T[s*768+q];
            #pragma unroll
            for (int o=16;o;o>>=1) sum += __shfl_xor_sync(~0u,sum,o);
            if (l==0) means[s] = sum*(1.0f/768.0f);
        }
        __syncthreads();
        #pragma unroll 1
        for (int g=0; g<3; g++){
            int d = g*256+t; float wl = wln[d];
            #pragma unroll
            for (int s=0;s<12;s++)
                g_Tc[((size_t)h*384 + s0 + s)*768 + d] = (T[s*768+d]-means[s])*wl;
        }
    }
}

// ---------------- K2: split-K SGEMM  C[384,768] = At[384,4608] @ Tc ----------
// 128x128 tile, BK=16, split-K=8, 256 threads, thread = 8m x 8n.
__global__ __launch_bounds__(256, 2) void k_gemm(){
    __shared__ __align__(16) float As[16*132];
    __shared__ __align__(16) float Bs[16*128];
    int m0 = blockIdx.x*128, n0 = blockIdx.y*128, z = blockIdx.z;
    int K0 = z*576;
    int t = threadIdx.x;
    int ty = t>>4, tx = t&15;
    unsigned long long acc[8][4];
    #pragma unroll
    for (int i=0;i<8;i++)
        #pragma unroll
        for (int j=0;j<4;j++) acc[i][j]=0ull;
    for (int ks=0; ks<36; ks++){
        int kb = K0 + ks*16;
        #pragma unroll
        for (int rep=0; rep<2; rep++){
            int idx = t + rep*256;
            int r = idx>>2, c = (idx&3)*4;
            float4 a4 = *(const float4*)(g_At + (size_t)(m0+r)*4608 + kb + c);
            As[(c+0)*132+r]=a4.x; As[(c+1)*132+r]=a4.y;
            As[(c+2)*132+r]=a4.z; As[(c+3)*132+r]=a4.w;
            int rb = idx>>5, cb = (idx&31)*4;
            *(float4*)&Bs[rb*128+cb] = *(const float4*)(g_Tc + (size_t)(kb+rb)*768 + n0 + cb);
        }
        __syncthreads();
        #pragma unroll
        for (int kk=0; kk<16; kk++){
            float4 a1 = *(float4*)&As[kk*132 + ty*8];
            float4 a2 = *(float4*)&As[kk*132 + ty*8 + 4];
            float4 b1 = *(float4*)&Bs[kk*128 + tx*8];
            float4 b2 = *(float4*)&Bs[kk*128 + tx*8 + 4];
            unsigned long long bv0=pack2(b1.x,b1.y), bv1=pack2(b1.z,b1.w);
            unsigned long long bv2=pack2(b2.x,b2.y), bv3=pack2(b2.z,b2.w);
            float av[8]={a1.x,a1.y,a1.z,a1.w,a2.x,a2.y,a2.z,a2.w};
            #pragma unroll
            for (int i=0;i<8;i++){
                unsigned long long ad = dup2(av[i]);
                fma2(acc[i][0],ad,bv0); fma2(acc[i][1],ad,bv1);
                fma2(acc[i][2],ad,bv2); fma2(acc[i][3],ad,bv3);
            }
        }
        __syncthreads();
    }
    #pragma unroll
    for (int i=0;i<8;i++){
        int row = m0 + ty*8 + i;
        float* dst = g_part + ((size_t)z*384 + row)*768 + n0 + tx*8;
        ulonglong2 v0; v0.x=acc[i][0]; v0.y=acc[i][1];
        ulonglong2 v1; v1.x=acc[i][2]; v1.y=acc[i][3];
        *(ulonglong2*)dst = v0;
        *(ulonglong2*)(dst+4) = v1;
    }
}

// ---------------- K3: resultant + resmn --------------------------------------
__global__ void k_res(const float* __restrict__ lnb, float* __restrict__ out_res){
    int k = blockIdx.x;
    float inv = g_inv[k];
    for (int d=threadIdx.x; d<768; d+=256){
        float s = 0.f;
        #pragma unroll
        for (int z=0; z<8; z++) s += g_part[((size_t)z*384 + k)*768 + d];
        float ao = s + g_hc[(size_t)k*768 + d] + g_biasc[d];
        float r  = ao*inv + lnb[d];
        out_res[(size_t)k*768 + d] = r;
        g_resmn[(size_t)k*768 + d] = 1e-6f - r;
    }
}

// ---------------- K4: main fused kernel --------------------------------------
// block = (s, k-quarter of 96). 192 threads; thread owns 4 d for all 96 k.
// 4-deep resmn prefetch ring; split fma chains; per-kk intra-warp butterfly;
// cross-warp stage deferred to a single-sync tail.
__global__ __launch_bounds__(192) void k_main(const float* __restrict__ attn,
                                              float* __restrict__ out){
    __shared__ __align__(16) unsigned long long cs2[96*12];  // dup'd attn[h,k,s]*inv[k]
    __shared__ float pn[96][6];
    __shared__ float pa[96][6];
    int s = blockIdx.x;
    int kbase = blockIdx.y*96;
    int t = threadIdx.x;

    // stage duplicated coefficients (1152 entries, 6 per thread)
    for (int idx=t; idx<1152; idx+=192){
        int kk = idx/12, h = idx - kk*12;
        int k = kbase + kk;
        float c = attn[(size_t)h*147456 + (size_t)k*384 + s] * g_inv[k];
        cs2[idx] = dup2(c);
    }

    int d0 = t*4;

    // register-resident Tc[h][d0..d0+3]
    unsigned long long tca[12], tcb[12];
    #pragma unroll
    for (int h=0; h<12; h++){
        ulonglong2 v = *(const ulonglong2*)(g_Tc + ((size_t)h*384 + s)*768 + d0);
        tca[h]=v.x; tcb[h]=v.y;
    }
    unsigned long long hca, hcb;
    {
        ulonglong2 v = *(const ulonglong2*)(g_hc + (size_t)s*768 + d0);
        unsigned long long iv = dup2(g_inv[s]);
        hca = mul2(v.x, iv); hcb = mul2(v.y, iv);
    }
    __syncthreads();

    int wid = t>>5, lane = t&31;
    float* out_tv = out + OFF_TV;
    const unsigned long long MSK = 0x7FFFFFFF7FFFFFFFULL;

    // 4-deep prefetch ring for resmn rows
    ulonglong2 ring[4];
    #pragma unroll
    for (int p=0; p<4; p++)
        ring[p] = *(const ulonglong2*)(g_resmn + (size_t)(kbase+p)*768 + d0);

    #pragma unroll 1
    for (int kk=0; kk<96; kk++){
        int k = kbase + kk;
        ulonglong2 rv = ring[kk&3];
        if (kk+4 < 96)
            ring[kk&3] = *(const ulonglong2*)(g_resmn + (size_t)(k+4)*768 + d0);

        // 12 pre-duplicated coefficients: 6 x LDS.128
        const ulonglong2* cp = (const ulonglong2*)&cs2[kk*12];
        ulonglong2 c01 = cp[0], c23 = cp[1], c45 = cp[2];
        ulonglong2 c67 = cp[3], c89 = cp[4], cAB = cp[5];
        unsigned long long cd[12] = { c01.x,c01.y, c23.x,c23.y, c45.x,c45.y,
                                      c67.x,c67.y, c89.x,c89.y, cAB.x,cAB.y };

        // split chains: two independent 6-FMA chains per half
        unsigned long long a0=0ull, a1=0ull, b0=0ull, b1=0ull;
        #pragma unroll
        for (int h=0; h<6; h++){
            fma2(a0, cd[h],   tca[h]);
            fma2(b0, cd[h],   tcb[h]);
            fma2(a1, cd[h+6], tca[h+6]);
            fma2(b1, cd[h+6], tcb[h+6]);
        }
        unsigned long long acc0 = add2(a0,a1);
        unsigned long long acc1 = add2(b0,b1);
        if (k==s){ acc0 = add2(acc0, hca); acc1 = add2(acc1, hcb); }

        // store tv_std (16B per thread, warp-contiguous 512B)
        ulonglong2 st; st.x=acc0; st.y=acc1;
        *(ulonglong2*)(out_tv + ((size_t)k*384 + s)*768 + d0) = st;

        // norm^2 partial
        unsigned long long n2 = 0ull;
        fma2(n2, acc0, acc0);
        fma2(n2, acc1, acc1);
        // |tv_std - resultant + eps| partial
        unsigned long long df0 = add2(acc0, rv.x) & MSK;
        unsigned long long df1 = add2(acc1, rv.y) & MSK;
        unsigned long long aa  = add2(df0, df1);

        float nlo,nhi,alo,ahi;
        unpack2(n2,nlo,nhi); unpack2(aa,alo,ahi);
        float sn = nlo+nhi, sa = alo+ahi;
        #pragma unroll
        for (int o=16;o;o>>=1){
            sn += __shfl_xor_sync(~0u,sn,o);
            sa += __shfl_xor_sync(~0u,sa,o);
        }
        if (lane==0){ pn[kk][wid]=sn; pa[kk][wid]=sa; }
    }
    __syncthreads();

    // tail: 192 tasks = {norm,abs} x 96 k; one thread each
    {
        int arr = t >= 96;
        int kk  = arr ? t-96 : t;
        int k   = kbase + kk;
        const float* buf = arr ? pa[kk] : pn[kk];
        float v = buf[0]+buf[1]+buf[2]+buf[3]+buf[4]+buf[5];
        if (arr) out[(size_t)k*384 + s] = -v;                   // importance
        else     out[OFF_NORM + (size_t)k*384 + s] = sqrtf(v);  // tv_norm
    }
}

// ---------------- launch ------------------------------------------------------
extern "C" void kernel_launch(void* const* d_in, const int* in_sizes, int n_in,
                              void* d_out, int out_size){
    (void)in_sizes; (void)n_in; (void)out_size;
    const float* value  = (const float*)d_in[0];
    const float* attn   = (const float*)d_in[1];
    const float* hidden = (const float*)d_in[2];
    const float* preln  = (const float*)d_in[3];
    const float* dw     = (const float*)d_in[4];
    const float* dbias  = (const float*)d_in[5];
    const float* wln    = (const float*)d_in[6];
    const float* lnb    = (const float*)d_in[7];
    float* out = (float*)d_out;

    k_prep<<<1153, 256>>>(preln, hidden, dbias, wln, attn, value, dw);
    k_gemm<<<dim3(3,6,8), 256>>>();
    k_res<<<384, 256>>>(lnb, out + OFF_RES);
    k_main<<<dim3(384,4), 192>>>(attn, out);
}

// round 8
// speedup vs baseline: 1.5474x; 1.1452x over previous
#include <cuda_runtime.h>
#include <cstdint>
#include <cstddef>

// Shapes: B=1, H=12, S=384, V=64, D=768
// Outputs (fp32, concatenated): importance[384,384] @0, tv_norm[384,384] @147456,
// tv_std[384,384,768] @294912, resultant[384,768] @113541120

#define OFF_NORM 147456
#define OFF_TV   294912
#define OFF_RES  113541120u

// ---------------- device scratch (no allocations allowed) -------------------
__device__ __align__(16) float g_Tc[12*384*768];    // [h][s][d]
__device__ __align__(16) float g_At[384*4608];      // [k][h*384+s] = attn[h,k,s]
__device__ __align__(16) float g_hc[384*768];       // (hidden - mean_d)*w_ln
__device__ __align__(16) float g_resmn[384*768];    // eps - resultant
__device__ __align__(16) float g_part[8*384*768];   // split-K GEMM partials
__device__ __align__(16) float g_gram[384*96];      // per-s Gram of {Tc[h],hc}: 91 used
__device__ __align__(16) float g_biasc[768];        // (bias - mean)*w_ln
__device__ __align__(16) float g_inv[384];          // 1/std(pre_ln, ddof=1)

// ---------------- f32x2 helpers ---------------------------------------------
__device__ __forceinline__ unsigned long long pack2(float lo, float hi){
    unsigned long long r; asm("mov.b64 %0, {%1, %2};" : "=l"(r) : "f"(lo), "f"(hi)); return r;
}
__device__ __forceinline__ unsigned long long dup2(float a){
    unsigned long long r; asm("mov.b64 %0, {%1, %1};" : "=l"(r) : "f"(a)); return r;
}
__device__ __forceinline__ void unpack2(unsigned long long v, float& lo, float& hi){
    asm("mov.b64 {%0, %1}, %2;" : "=f"(lo), "=f"(hi) : "l"(v));
}
__device__ __forceinline__ void fma2(unsigned long long& acc, unsigned long long a, unsigned long long b){
    asm("fma.rn.f32x2 %0, %1, %2, %0;" : "+l"(acc) : "l"(a), "l"(b));
}
__device__ __forceinline__ unsigned long long add2(unsigned long long a, unsigned long long b){
    unsigned long long r; asm("add.rn.f32x2 %0, %1, %2;" : "=l"(r) : "l"(a), "l"(b)); return r;
}
__device__ __forceinline__ unsigned long long mul2(unsigned long long a, unsigned long long b){
    unsigned long long r; asm("mul.rn.f32x2 %0, %1, %2;" : "=l"(r) : "l"(a), "l"(b)); return r;
}

// ---------------- K1: fused prep (stats | attn-transpose | Tc) ---------------
__global__ __launch_bounds__(256) void k_prep(const float* __restrict__ preln,
                                              const float* __restrict__ hidden,
                                              const float* __restrict__ dbias,
                                              const float* __restrict__ wln,
                                              const float* __restrict__ attn,
                                              const float* __restrict__ value,
                                              const float* __restrict__ dw){
    int bid = blockIdx.x, t = threadIdx.x;
    if (bid <= 384){
        __shared__ float w1[8], w2[8], sres[2];
        int lane = t & 31, wid = t >> 5;
        int b = bid;
        if (b < 384){
            const float* row = preln + (size_t)b*768;
            float s1=0.f, s2=0.f;
            for (int d=t; d<768; d+=256){ float x=row[d]; s1+=x; s2=fmaf(x,x,s2); }
            for (int o=16;o;o>>=1){ s1+=__shfl_xor_sync(~0u,s1,o); s2+=__shfl_xor_sync(~0u,s2,o); }
            if (lane==0){ w1[wid]=s1; w2[wid]=s2; }
            __syncthreads();
            if (t==0){
                float a=0.f,c=0.f;
                #pragma unroll
                for (int j=0;j<8;j++){ a+=w1[j]; c+=w2[j]; }
                float mean = a*(1.0f/768.0f);
                float var  = (c - a*mean)*(1.0f/767.0f);
                float inv  = rsqrtf(var);
                g_inv[b]=inv; sres[0]=inv;
            }
            __syncthreads();
            const float* hr = hidden + (size_t)b*768;
            float hs=0.f;
            for (int d=t; d<768; d+=256) hs += hr[d];
            for (int o=16;o;o>>=1) hs += __shfl_xor_sync(~0u,hs,o);
            __syncthreads();
            if (lane==0) w1[wid]=hs;
            __syncthreads();
            if (t==0){
                float a=0.f;
                #pragma unroll
                for (int j=0;j<8;j++) a+=w1[j];
                sres[1]=a*(1.0f/768.0f);
            }
            __syncthreads();
            float hmean = sres[1];
            for (int d=t; d<768; d+=256)
                g_hc[(size_t)b*768+d] = (hr[d]-hmean)*wln[d];
        } else {
            float s=0.f;
            for (int d=t; d<768; d+=256) s += dbias[d];
            for (int o=16;o;o>>=1) s += __shfl_xor_sync(~0u,s,o);
            if (lane==0) w1[wid]=s;
            __syncthreads();
            if (t==0){
                float a=0.f;
                #pragma unroll
                for (int j=0;j<8;j++) a+=w1[j];
                sres[0]=a*(1.0f/768.0f);
            }
            __syncthreads();
            float mean = sres[0];
            for (int d=t; d<768; d+=256) g_biasc[d] = (dbias[d]-mean)*wln[d];
        }
    } else if (bid <= 768){
        int k = bid - 385;
        float4* dst = (float4*)(g_At + (size_t)k*4608);
        for (int idx=t; idx<1152; idx+=256){
            int h = idx/96, j = idx - h*96;
            dst[h*96 + j] = ((const float4*)(attn + ((size_t)h*384 + k)*384))[j];
        }
    } else {
        __shared__ __align__(16) float val[12*64];
        __shared__ __align__(16) float T[12*768];
        __shared__ float means[12];
        int i = bid - 769;           // 0..383
        int s0 = (i & 31)*12, h = i >> 5;
        if (t < 192)
            ((float4*)val)[t] = ((const float4*)(value + ((size_t)h*384 + s0)*64))[t];
        __syncthreads();
        const unsigned long long* val2 = (const unsigned long long*)val;
        #pragma unroll 1
        for (int g=0; g<3; g++){
            int d = g*256 + t;
            unsigned long long w2r[32];
            const unsigned long long* wr = (const unsigned long long*)(dw + ((size_t)d*12 + h)*64);
            #pragma unroll
            for (int q=0;q<32;q++) w2r[q]=wr[q];
            #pragma unroll 1
            for (int s=0;s<12;s++){
                unsigned long long acc = 0ull;
                #pragma unroll
                for (int q=0;q<32;q++) fma2(acc, w2r[q], val2[s*32+q]);
                float lo,hi; unpack2(acc,lo,hi);
                T[s*768 + d] = lo + hi;
            }
        }
        __syncthreads();
        int w = t>>5, l = t&31;
        for (int s=w; s<12; s+=8){
            float sum=0.f;
            for (int q=l; q<768; q+=32) sum += T[s*768+q];
            #pragma unroll
            for (int o=16;o;o>>=1) sum += __shfl_xor_sync(~0u,sum,o);
            if (l==0) means[s] = sum*(1.0f/768.0f);
        }
        __syncthreads();
        #pragma unroll 1
        for (int g=0; g<3; g++){
            int d = g*256+t; float wl = wln[d];
            #pragma unroll
            for (int s=0;s<12;s++)
                g_Tc[((size_t)h*384 + s0 + s)*768 + d] = (T[s*768+d]-means[s])*wl;
        }
    }
}

// ---------------- K2: split-K SGEMM  C[384,768] = At[384,4608] @ Tc ----------
__global__ __launch_bounds__(256, 2) void k_gemm(){
    __shared__ __align__(16) float As[16*132];
    __shared__ __align__(16) float Bs[16*128];
    int m0 = blockIdx.x*128, n0 = blockIdx.y*128, z = blockIdx.z;
    int K0 = z*576;
    int t = threadIdx.x;
    int ty = t>>4, tx = t&15;
    unsigned long long acc[8][4];
    #pragma unroll
    for (int i=0;i<8;i++)
        #pragma unroll
        for (int j=0;j<4;j++) acc[i][j]=0ull;
    for (int ks=0; ks<36; ks++){
        int kb = K0 + ks*16;
        #pragma unroll
        for (int rep=0; rep<2; rep++){
            int idx = t + rep*256;
            int r = idx>>2, c = (idx&3)*4;
            float4 a4 = *(const float4*)(g_At + (size_t)(m0+r)*4608 + kb + c);
            As[(c+0)*132+r]=a4.x; As[(c+1)*132+r]=a4.y;
            As[(c+2)*132+r]=a4.z; As[(c+3)*132+r]=a4.w;
            int rb = idx>>5, cb = (idx&31)*4;
            *(float4*)&Bs[rb*128+cb] = *(const float4*)(g_Tc + (size_t)(kb+rb)*768 + n0 + cb);
        }
        __syncthreads();
        #pragma unroll
        for (int kk=0; kk<16; kk++){
            float4 a1 = *(float4*)&As[kk*132 + ty*8];
            float4 a2 = *(float4*)&As[kk*132 + ty*8 + 4];
            float4 b1 = *(float4*)&Bs[kk*128 + tx*8];
            float4 b2 = *(float4*)&Bs[kk*128 + tx*8 + 4];
            unsigned long long bv0=pack2(b1.x,b1.y), bv1=pack2(b1.z,b1.w);
            unsigned long long bv2=pack2(b2.x,b2.y), bv3=pack2(b2.z,b2.w);
            float av[8]={a1.x,a1.y,a1.z,a1.w,a2.x,a2.y,a2.z,a2.w};
            #pragma unroll
            for (int i=0;i<8;i++){
                unsigned long long ad = dup2(av[i]);
                fma2(acc[i][0],ad,bv0); fma2(acc[i][1],ad,bv1);
                fma2(acc[i][2],ad,bv2); fma2(acc[i][3],ad,bv3);
            }
        }
        __syncthreads();
    }
    #pragma unroll
    for (int i=0;i<8;i++){
        int row = m0 + ty*8 + i;
        float* dst = g_part + ((size_t)z*384 + row)*768 + n0 + tx*8;
        ulonglong2 v0; v0.x=acc[i][0]; v0.y=acc[i][1];
        ulonglong2 v1; v1.x=acc[i][2]; v1.y=acc[i][3];
        *(ulonglong2*)dst = v0;
        *(ulonglong2*)(dst+4) = v1;
    }
}

// ---------------- K3: resultant + resmn --------------------------------------
__global__ void k_res(const float* __restrict__ lnb, float* __restrict__ out_res){
    int k = blockIdx.x;
    float inv = g_inv[k];
    for (int d=threadIdx.x; d<768; d+=256){
        float s = 0.f;
        #pragma unroll
        for (int z=0; z<8; z++) s += g_part[((size_t)z*384 + k)*768 + d];
        float ao = s + g_hc[(size_t)k*768 + d] + g_biasc[d];
        float r  = ao*inv + lnb[d];
        out_res[(size_t)k*768 + d] = r;
        g_resmn[(size_t)k*768 + d] = 1e-6f - r;
    }
}

// ---------------- K3b: per-s Gram of the 13 vectors {Tc[0..11], hc} ---------
// g_gram[s][p], p enumerates (i<=j) over 13 vectors: 91 entries.
// (i,j<12): Tc Gram; (i,12): x[i]=sum Tc_i*hc; (12,12): q=sum hc^2.
__global__ __launch_bounds__(256) void k_gram(){
    __shared__ __align__(16) float V[13][768];
    int s = blockIdx.x, t = threadIdx.x;
    for (int idx=t; idx<13*768; idx+=256){
        int r = idx/768, d = idx - r*768;
        V[r][d] = (r<12) ? g_Tc[((size_t)r*384+s)*768+d] : g_hc[(size_t)s*768+d];
    }
    __syncthreads();
    int w = t>>5, lane = t&31;
    for (int p=w; p<91; p+=8){
        int i=0, rem=p;
        while (rem >= 13-i){ rem -= 13-i; i++; }
        int j = i + rem;
        const float* vi = V[i];
        const float* vj = V[j];
        float acc=0.f;
        for (int d=lane; d<768; d+=32) acc = fmaf(vi[d], vj[d], acc);
        #pragma unroll
        for (int o=16;o;o>>=1) acc += __shfl_xor_sync(~0u,acc,o);
        if (lane==0) g_gram[s*96+p] = acc;
    }
}

// ---------------- K4: main fused kernel --------------------------------------
// block = (s, k-quarter of 96). 192 threads; thread owns 4 d for all 96 k.
// Mainloop: GEMV + tv_std store + abs-sum with 3-step butterfly.
// Tail: norm via Gram quadratic form (t<96) + abs-sum finish (t>=96).
__global__ __launch_bounds__(192) void k_main(const float* __restrict__ attn,
                                              float* __restrict__ out){
    __shared__ __align__(16) unsigned long long cs2[96*12];  // dup'd attn[h,k,s]*inv[k]
    __shared__ float pa[96][24];                             // abs partials [kk][w*4+lane]
    __shared__ float Gs[91];
    int s = blockIdx.x;
    int kbase = blockIdx.y*96;
    int t = threadIdx.x;

    // stage duplicated coefficients (1152 entries, 6 per thread)
    for (int idx=t; idx<1152; idx+=192){
        int kk = idx/12, h = idx - kk*12;
        int k = kbase + kk;
        float c = attn[(size_t)h*147456 + (size_t)k*384 + s] * g_inv[k];
        cs2[idx] = dup2(c);
    }
    if (t < 91) Gs[t] = g_gram[s*96 + t];

    int d0 = t*4;

    // register-resident Tc[h][d0..d0+3]
    unsigned long long tca[12], tcb[12];
    #pragma unroll
    for (int h=0; h<12; h++){
        ulonglong2 v = *(const ulonglong2*)(g_Tc + ((size_t)h*384 + s)*768 + d0);
        tca[h]=v.x; tcb[h]=v.y;
    }
    unsigned long long hca, hcb;
    {
        ulonglong2 v = *(const ulonglong2*)(g_hc + (size_t)s*768 + d0);
        unsigned long long iv = dup2(g_inv[s]);
        hca = mul2(v.x, iv); hcb = mul2(v.y, iv);
    }
    __syncthreads();

    int wid = t>>5, lane = t&31;
    float* out_tv = out + OFF_TV;

    // 4-deep prefetch ring for resmn rows
    ulonglong2 ring[4];
    #pragma unroll
    for (int p=0; p<4; p++)
        ring[p] = *(const ulonglong2*)(g_resmn + (size_t)(kbase+p)*768 + d0);

    #pragma unroll 2
    for (int kk=0; kk<96; kk++){
        int k = kbase + kk;
        ulonglong2 rv = ring[kk&3];
        if (kk+4 < 96)
            ring[kk&3] = *(const ulonglong2*)(g_resmn + (size_t)(k+4)*768 + d0);

        // 12 pre-duplicated coefficients: 6 x LDS.128 (broadcast)
        const ulonglong2* cp = (const ulonglong2*)&cs2[kk*12];
        ulonglong2 c01 = cp[0], c23 = cp[1], c45 = cp[2];
        ulonglong2 c67 = cp[3], c89 = cp[4], cAB = cp[5];
        unsigned long long cd[12] = { c01.x,c01.y, c23.x,c23.y, c45.x,c45.y,
                                      c67.x,c67.y, c89.x,c89.y, cAB.x,cAB.y };

        // split chains: two independent 6-FMA chains per half
        unsigned long long a0=0ull, a1=0ull, b0=0ull, b1=0ull;
        #pragma unroll
        for (int h=0; h<6; h++){
            fma2(a0, cd[h],   tca[h]);
            fma2(b0, cd[h],   tcb[h]);
            fma2(a1, cd[h+6], tca[h+6]);
            fma2(b1, cd[h+6], tcb[h+6]);
        }
        unsigned long long acc0 = add2(a0,a1);
        unsigned long long acc1 = add2(b0,b1);
        if (k==s){ acc0 = add2(acc0, hca); acc1 = add2(acc1, hcb); }

        // streaming store tv_std (16B per thread, warp-contiguous 512B)
        {
            float* dst = out_tv + ((size_t)k*384 + s)*768 + d0;
            asm volatile("st.global.cs.v2.u64 [%0], {%1, %2};"
                         :: "l"(dst), "l"(acc0), "l"(acc1) : "memory");
        }

        // |tv_std - resultant + eps| partial (abs folds into FADD operands)
        unsigned long long df0 = add2(acc0, rv.x);
        unsigned long long df1 = add2(acc1, rv.y);
        float x0,x1,x2,x3;
        unpack2(df0,x0,x1); unpack2(df1,x2,x3);
        float sa = (fabsf(x0)+fabsf(x1)) + (fabsf(x2)+fabsf(x3));
        // 3-step butterfly; lanes 0..3 hold 4 disjoint 8-lane sums
        sa += __shfl_xor_sync(~0u, sa, 16);
        sa += __shfl_xor_sync(~0u, sa, 8);
        sa += __shfl_xor_sync(~0u, sa, 4);
        if (lane < 4) pa[kk][wid*4 + lane] = sa;
    }
    __syncthreads();

    if (t < 96){
        // tv_norm via Gram quadratic form
        int kk = t, k = kbase + kk;
        float c[12];
        #pragma unroll
        for (int h=0; h<12; h++) c[h] = ((const float*)&cs2[kk*12+h])[0];
        float inv_s = g_inv[s];
        bool diag = (k==s);
        float acc = 0.f;
        int p = 0;
        #pragma unroll
        for (int i=0; i<12; i++){
            float ci = c[i];
            acc = fmaf(ci*ci, Gs[p], acc); p++;
            #pragma unroll
            for (int j=i+1; j<12; j++){ acc = fmaf(2.0f*ci*c[j], Gs[p], acc); p++; }
            if (diag) acc = fmaf(2.0f*inv_s*ci, Gs[p], acc);
            p++;
        }
        if (diag) acc = fmaf(inv_s*inv_s, Gs[90], acc);
        out[OFF_NORM + (size_t)k*384 + s] = sqrtf(fmaxf(acc, 0.f));
    } else {
        // importance: finish the abs-sum
        int kk = t - 96, k = kbase + kk;
        const float* buf = pa[kk];
        float v = 0.f;
        #pragma unroll
        for (int j=0; j<24; j++) v += buf[j];
        out[(size_t)k*384 + s] = -v;
    }
}

// ---------------- launch ------------------------------------------------------
extern "C" void kernel_launch(void* const* d_in, const int* in_sizes, int n_in,
                              void* d_out, int out_size){
    (void)in_sizes; (void)n_in; (void)out_size;
    const float* value  = (const float*)d_in[0];
    const float* attn   = (const float*)d_in[1];
    const float* hidden = (const float*)d_in[2];
    const float* preln  = (const float*)d_in[3];
    const float* dw     = (const float*)d_in[4];
    const float* dbias  = (const float*)d_in[5];
    const float* wln    = (const float*)d_in[6];
    const float* lnb    = (const float*)d_in[7];
    float* out = (float*)d_out;

    k_prep<<<1153, 256>>>(preln, hidden, dbias, wln, attn, value, dw);
    k_gemm<<<dim3(3,6,8), 256>>>();
    k_res<<<384, 256>>>(lnb, out + OFF_RES);
    k_gram<<<384, 256>>>();
    k_main<<<dim3(384,4), 192>>>(attn, out);
}